// round 15
// baseline (speedup 1.0000x reference)
#include <cuda_runtime.h>
#include <cuda_bf16.h>
#include <cuda_fp16.h>
#include <math.h>
#include <stdint.h>

// Problem constants
#define BATCH   2
#define SEQ     2048
#define HID     4096
#define NHEADS  32
#define NKV     8
#define NREP    4
#define HD      128
#define SCALING 0.08838834764831845f           // 128^-0.5
#define QSCALE  0.1275429555686623f            // SCALING * log2(e)
#define NEG_BIG (-1.0e30f)
#define NPERSIST 296                            // 2 CTAs/SM x 148 SMs

// ---------------------------------------------------------------------------
// Scratch (device globals)
// ---------------------------------------------------------------------------
__device__ float g_q[BATCH * NHEADS * SEQ * HD];
__device__ float g_k[BATCH * NKV * SEQ * HD];
__device__ float g_v[BATCH * NKV * SEQ * HD];

__device__ __half g_xf16[4096 * 4096];
__device__ __half g_wqkvT_hi[6144 * 4096], g_wqkvT_lo[6144 * 4096];
__device__ __half g_woT_hi[4096 * 4096];
__device__ __half g_af16[4096 * 4096];

__device__ __half g_qhi[BATCH * NHEADS * SEQ * HD], g_qlo[BATCH * NHEADS * SEQ * HD];
__device__ __half g_kf16[BATCH * NKV * SEQ * HD];
__device__ __half g_vf16[BATCH * NKV * SEQ * HD];

// ---------------------------------------------------------------------------
// PTX helpers
// ---------------------------------------------------------------------------
__device__ __forceinline__ uint32_t smem_u32(const void* p) {
    uint32_t a;
    asm("{ .reg .u64 t; cvta.to.shared.u64 t, %1; cvt.u32.u64 %0, t; }"
        : "=r"(a) : "l"(p));
    return a;
}

#define CP_ASYNC16(dst, src) \
    asm volatile("cp.async.cg.shared.global [%0], [%1], 16;" :: "r"(dst), "l"(src) : "memory")
#define CP_COMMIT() asm volatile("cp.async.commit_group;" ::: "memory")
#define CP_WAIT0()  asm volatile("cp.async.wait_group 0;" ::: "memory")
#define CP_WAIT1()  asm volatile("cp.async.wait_group 1;" ::: "memory")

__device__ __forceinline__ void ldsm4(uint32_t* r, uint32_t addr) {
    asm volatile("ldmatrix.sync.aligned.m8n8.x4.shared.b16 {%0,%1,%2,%3}, [%4];"
        : "=r"(r[0]), "=r"(r[1]), "=r"(r[2]), "=r"(r[3]) : "r"(addr));
}
__device__ __forceinline__ void ldsm4t(uint32_t* r, uint32_t addr) {
    asm volatile("ldmatrix.sync.aligned.m8n8.x4.trans.shared.b16 {%0,%1,%2,%3}, [%4];"
        : "=r"(r[0]), "=r"(r[1]), "=r"(r[2]), "=r"(r[3]) : "r"(addr));
}

__device__ __forceinline__ void mma_hf(float* d, const uint32_t* a, const uint32_t* b) {
    asm volatile(
        "mma.sync.aligned.m16n8k16.row.col.f32.f16.f16.f32 "
        "{%0,%1,%2,%3}, {%4,%5,%6,%7}, {%8,%9}, {%0,%1,%2,%3};"
        : "+f"(d[0]), "+f"(d[1]), "+f"(d[2]), "+f"(d[3])
        : "r"(a[0]), "r"(a[1]), "r"(a[2]), "r"(a[3]), "r"(b[0]), "r"(b[1]));
}

__device__ __forceinline__ uint32_t sw64(uint32_t off) {
    return off ^ ((off >> 3) & 0x30);
}
__device__ __forceinline__ uint32_t sw128(uint32_t off) {
    return off ^ ((off >> 3) & 0x70);
}

__device__ __forceinline__ uint32_t packhf(float lo, float hi) {
    uint32_t r;
    asm("cvt.rn.f16x2.f32 %0, %1, %2;" : "=r"(r) : "f"(hi), "f"(lo));
    return r;
}

__device__ __forceinline__ float ex2(float x) {
    float r;
    asm("ex2.approx.f32 %0, %1;" : "=f"(r) : "f"(x));
    return r;
}

// ---------------------------------------------------------------------------
// prepW: z=0..2 merged QKV weight transpose+split; z=3 wo (hi only); z=4 X cvt.
// ---------------------------------------------------------------------------
__global__ void prepW_kernel(
    const float* __restrict__ X,
    const float* __restrict__ wq, const float* __restrict__ wk,
    const float* __restrict__ wv, const float* __restrict__ wo,
    __half* __restrict__ Xf,
    __half* __restrict__ qkvh, __half* __restrict__ qkvl,
    __half* __restrict__ oh)
{
    const int z = blockIdx.z;
    const int tx = threadIdx.x, ty = threadIdx.y;

    if (z == 4) {
        size_t g = ((size_t)blockIdx.y * gridDim.x + blockIdx.x) * 256 + (ty * 32 + tx);
        size_t i = g * 4;
        float4 v = *(const float4*)(X + i);
        uint32_t p0 = packhf(v.x, v.y);
        uint32_t p1 = packhf(v.z, v.w);
        *(uint2*)(Xf + i) = make_uint2(p0, p1);
        return;
    }

    const float* in;
    int N, rbase;
    bool want_lo;
    __half *hi, *lo;
    if (z == 0)      { in = wq; hi = qkvh; lo = qkvl; N = 4096; rbase = 0;    want_lo = true; }
    else if (z == 1) { in = wk; hi = qkvh; lo = qkvl; N = 1024; rbase = 4096; want_lo = true; }
    else if (z == 2) { in = wv; hi = qkvh; lo = qkvl; N = 1024; rbase = 5120; want_lo = true; }
    else             { in = wo; hi = oh;   lo = oh;   N = 4096; rbase = 0;    want_lo = false; }
    const int n0 = blockIdx.x * 32;
    if (n0 >= N) return;
    const int K = 4096;
    const int k0 = blockIdx.y * 32;

    __shared__ float t[32][33];
    for (int i = ty; i < 32; i += 8)
        t[i][tx] = in[(size_t)(k0 + i) * N + n0 + tx];
    __syncthreads();
    for (int i = ty; i < 32; i += 8) {
        float a = t[tx][i];
        __half h = __float2half_rn(a);
        size_t o = (size_t)(rbase + n0 + i) * K + k0 + tx;
        hi[o] = h;
        if (want_lo)
            lo[o] = __float2half_rn(a - __half2float(h));
    }
}

// ---------------------------------------------------------------------------
// prep: ropeQ (fp16 hi/lo) + ropeK (fp16 single) + cvtV (fp16)
// ---------------------------------------------------------------------------
#define PREP_QT (BATCH * NHEADS * SEQ * 64)
#define PREP_KT (BATCH * NKV * SEQ * 64)
#define PREP_VT (BATCH * NKV * SEQ * HD / 4)

__global__ void prep_kernel(
    const float* __restrict__ Qb, const float* __restrict__ Kb,
    const float* __restrict__ Vb,
    const float* __restrict__ cosb, const float* __restrict__ sinb,
    __half* __restrict__ FQh, __half* __restrict__ FQl,
    __half* __restrict__ FKf, __half* __restrict__ Vf)
{
    int idx = blockIdx.x * blockDim.x + threadIdx.x;
    if (idx < PREP_QT) {
        const int d = idx & 63;
        const int row = idx >> 6;
        const int s = row & (SEQ - 1);
        const int b = (row / SEQ) / NHEADS;
        const float* xr = Qb + (size_t)row * HD;
        const float* cb = cosb + ((size_t)b * SEQ + s) * HD;
        const float* sb = sinb + ((size_t)b * SEQ + s) * HD;
        const float x0 = xr[d];
        const float x1 = xr[d + 64];
        const float y0 = (x0 * cb[d]      - x1 * sb[d])      * QSCALE;
        const float y1 = (x1 * cb[d + 64] + x0 * sb[d + 64]) * QSCALE;
        const size_t o = (size_t)row * HD + d;
        __half h0 = __float2half_rn(y0);
        __half h1 = __float2half_rn(y1);
        FQh[o]      = h0;
        FQh[o + 64] = h1;
        FQl[o]      = __float2half_rn(y0 - __half2float(h0));
        FQl[o + 64] = __float2half_rn(y1 - __half2float(h1));
    } else if (idx < PREP_QT + PREP_KT) {
        int i2 = idx - PREP_QT;
        const int d = i2 & 63;
        const int row = i2 >> 6;
        const int s = row & (SEQ - 1);
        const int b = (row / SEQ) / NKV;
        const float* xr = Kb + (size_t)row * HD;
        const float* cb = cosb + ((size_t)b * SEQ + s) * HD;
        const float* sb = sinb + ((size_t)b * SEQ + s) * HD;
        const float x0 = xr[d];
        const float x1 = xr[d + 64];
        const float y0 = x0 * cb[d]      - x1 * sb[d];
        const float y1 = x1 * cb[d + 64] + x0 * sb[d + 64];
        const size_t o = (size_t)row * HD + d;
        FKf[o]      = __float2half_rn(y0);
        FKf[o + 64] = __float2half_rn(y1);
    } else if (idx < PREP_QT + PREP_KT + PREP_VT) {
        int i = (idx - PREP_QT - PREP_KT) * 4;
        float4 v = *(const float4*)(Vb + i);
        uint32_t p0 = packhf(v.x, v.y);
        uint32_t p1 = packhf(v.z, v.w);
        *(uint2*)(Vf + i) = make_uint2(p0, p1);
    }
}

// ---------------------------------------------------------------------------
// Persistent QKV GEMM: BM=BN=128, BK=64, 256 thr, 2 CTAs/SM, 2-pass fp16.
// 296 CTAs loop over 48x32 = 1536 tiles.
// ---------------------------------------------------------------------------
#define GQKV_SMEM (2 * 49152)
#define QKV_TILES (48 * 32)

__global__ __launch_bounds__(256, 2) void gemm_qkv(
    const __half* __restrict__ A,
    const __half* __restrict__ Bhi, const __half* __restrict__ Blo,
    float* __restrict__ Qo, float* __restrict__ Ko, float* __restrict__ Vo,
    int M, int N, int K)
{
    extern __shared__ char dsm[];
    const uint32_t sm_base = smem_u32(dsm);

    const int tid = threadIdx.x;
    const int wid = tid >> 5;
    const int lane = tid & 31;
    const int wm = wid & 3;
    const int wn = wid >> 2;

    const uint32_t a_row = wm * 32 + (lane & 15);
    const uint32_t a_c16 = (lane >> 4) * 16;
    const uint32_t b_row = wn * 64 + ((lane >> 4) & 1) * 8 + (lane & 7);
    const uint32_t b_c16 = ((lane >> 3) & 1) * 16;
    const int NC = K >> 6;

    for (int t = blockIdx.x; t < QKV_TILES; t += NPERSIST) {
        const int m0 = (t / 48) * 128;
        const int n0 = (t % 48) * 128;

        auto load_chunk = [&](int stage, int c) {
            const int k0 = c << 6;
            const uint32_t stb = sm_base + stage * 49152u;
#pragma unroll
            for (int it = 0; it < 12; it++) {
                int g = tid + it * 256;
                int arr = g >> 10;
                int rem = g & 1023;
                int r = rem >> 3;
                int gg = rem & 7;
                int rowg = (arr == 0 ? m0 : n0) + r;
                const __half* base = (arr == 0) ? A : (arr == 1 ? Bhi : Blo);
                const __half* src = base + (size_t)rowg * K + k0 + gg * 8;
                uint32_t off = sw128((uint32_t)(r * 128 + gg * 16));
                CP_ASYNC16(stb + arr * 16384u + off, src);
            }
            CP_COMMIT();
        };

        float acc[2][8][4];
#pragma unroll
        for (int mt = 0; mt < 2; mt++)
#pragma unroll
            for (int nt = 0; nt < 8; nt++)
#pragma unroll
                for (int i = 0; i < 4; i++) acc[mt][nt][i] = 0.f;

        load_chunk(0, 0);

        for (int c = 0; c < NC; c++) {
            if (c + 1 < NC) {
                load_chunk((c + 1) & 1, c + 1);
                CP_WAIT1();
            } else {
                CP_WAIT0();
            }
            __syncthreads();

            const uint32_t stb = sm_base + (uint32_t)(c & 1) * 49152u;
            const uint32_t Ab = stb, Bh = stb + 16384u, Bl = stb + 32768u;

#pragma unroll
            for (int kt = 0; kt < 4; kt++) {
                uint32_t af[2][4], bhf[4][4], blf[4][4];
#pragma unroll
                for (int mt = 0; mt < 2; mt++) {
                    uint32_t off = sw128((a_row + mt * 16) * 128 + kt * 32 + a_c16);
                    ldsm4(af[mt], Ab + off);
                }
#pragma unroll
                for (int p = 0; p < 4; p++) {
                    uint32_t off = sw128((b_row + p * 16) * 128 + kt * 32 + b_c16);
                    ldsm4(bhf[p], Bh + off);
                    ldsm4(blf[p], Bl + off);
                }
#pragma unroll
                for (int mt = 0; mt < 2; mt++)
#pragma unroll
                    for (int nt = 0; nt < 8; nt++)
                        mma_hf(acc[mt][nt], af[mt], &bhf[nt >> 1][(nt & 1) * 2]);
#pragma unroll
                for (int mt = 0; mt < 2; mt++)
#pragma unroll
                    for (int nt = 0; nt < 8; nt++)
                        mma_hf(acc[mt][nt], af[mt], &blf[nt >> 1][(nt & 1) * 2]);
            }
            __syncthreads();
        }

        const int mr = m0 + wm * 32 + (lane >> 2);
        const int nc = n0 + wn * 64 + (lane & 3) * 2;
#pragma unroll
        for (int mt = 0; mt < 2; mt++) {
#pragma unroll
            for (int nt = 0; nt < 8; nt++) {
#pragma unroll
                for (int half = 0; half < 2; half++) {
                    const int m = mr + mt * 16 + half * 8;
                    const int n = nc + nt * 8;
                    float2 v = make_float2(acc[mt][nt][half * 2], acc[mt][nt][half * 2 + 1]);
                    const int b = m >> 11;
                    const int s = m & (SEQ - 1);
                    const int d = n & (HD - 1);
                    if (n < 4096) {
                        const int h = n >> 7;
                        *(float2*)&Qo[((size_t)(b * NHEADS + h) * SEQ + s) * HD + d] = v;
                    } else if (n < 5120) {
                        const int kv = (n - 4096) >> 7;
                        *(float2*)&Ko[((size_t)(b * NKV + kv) * SEQ + s) * HD + d] = v;
                    } else {
                        const int kv = (n - 5120) >> 7;
                        *(float2*)&Vo[((size_t)(b * NKV + kv) * SEQ + s) * HD + d] = v;
                    }
                }
            }
        }
    }
}

// ---------------------------------------------------------------------------
// Persistent O-projection GEMM: BM=BN=128, BK=64, 256 thr, single-pass fp16.
// 296 CTAs loop over 32x32 = 1024 tiles.
// ---------------------------------------------------------------------------
#define GO_SMEM (2 * 32768)
#define O_TILES (32 * 32)

__global__ __launch_bounds__(256, 2) void gemm_o(
    const __half* __restrict__ A, const __half* __restrict__ B,
    float* __restrict__ C, int M, int N, int K)
{
    extern __shared__ char dsm[];
    const uint32_t sm_base = smem_u32(dsm);

    const int tid = threadIdx.x;
    const int wid = tid >> 5;
    const int lane = tid & 31;
    const int wm = wid & 3;
    const int wn = wid >> 2;

    const uint32_t a_row = wm * 32 + (lane & 15);
    const uint32_t a_c16 = (lane >> 4) * 16;
    const uint32_t b_row = wn * 64 + ((lane >> 4) & 1) * 8 + (lane & 7);
    const uint32_t b_c16 = ((lane >> 3) & 1) * 16;
    const int NC = K >> 6;

    for (int t = blockIdx.x; t < O_TILES; t += NPERSIST) {
        const int m0 = (t / 32) * 128;
        const int n0 = (t % 32) * 128;

        auto load_chunk = [&](int stage, int c) {
            const int k0 = c << 6;
            const uint32_t stb = sm_base + stage * 32768u;
#pragma unroll
            for (int it = 0; it < 8; it++) {
                int g = tid + it * 256;
                int arr = g >> 10;
                int rem = g & 1023;
                int r = rem >> 3;
                int gg = rem & 7;
                int rowg = (arr == 0 ? m0 : n0) + r;
                const __half* src = (arr == 0 ? A : B) + (size_t)rowg * K + k0 + gg * 8;
                uint32_t off = sw128((uint32_t)(r * 128 + gg * 16));
                CP_ASYNC16(stb + arr * 16384u + off, src);
            }
            CP_COMMIT();
        };

        float acc[2][8][4];
#pragma unroll
        for (int mt = 0; mt < 2; mt++)
#pragma unroll
            for (int nt = 0; nt < 8; nt++)
#pragma unroll
                for (int i = 0; i < 4; i++) acc[mt][nt][i] = 0.f;

        load_chunk(0, 0);

        for (int c = 0; c < NC; c++) {
            if (c + 1 < NC) {
                load_chunk((c + 1) & 1, c + 1);
                CP_WAIT1();
            } else {
                CP_WAIT0();
            }
            __syncthreads();

            const uint32_t stb = sm_base + (uint32_t)(c & 1) * 32768u;
            const uint32_t Ab = stb, Bb = stb + 16384u;

#pragma unroll
            for (int kt = 0; kt < 4; kt++) {
                uint32_t af[2][4], bf[4][4];
#pragma unroll
                for (int mt = 0; mt < 2; mt++) {
                    uint32_t off = sw128((a_row + mt * 16) * 128 + kt * 32 + a_c16);
                    ldsm4(af[mt], Ab + off);
                }
#pragma unroll
                for (int p = 0; p < 4; p++) {
                    uint32_t off = sw128((b_row + p * 16) * 128 + kt * 32 + b_c16);
                    ldsm4(bf[p], Bb + off);
                }
#pragma unroll
                for (int mt = 0; mt < 2; mt++)
#pragma unroll
                    for (int nt = 0; nt < 8; nt++)
                        mma_hf(acc[mt][nt], af[mt], &bf[nt >> 1][(nt & 1) * 2]);
            }
            __syncthreads();
        }

        const int mr = m0 + wm * 32 + (lane >> 2);
        const int nc = n0 + wn * 64 + (lane & 3) * 2;
#pragma unroll
        for (int mt = 0; mt < 2; mt++)
#pragma unroll
            for (int nt = 0; nt < 8; nt++)
#pragma unroll
                for (int half = 0; half < 2; half++) {
                    const int m = mr + mt * 16 + half * 8;
                    const int n = nc + nt * 8;
                    *(float2*)&C[(size_t)m * N + n] =
                        make_float2(acc[mt][nt][half * 2], acc[mt][nt][half * 2 + 1]);
                }
    }
}

// ---------------------------------------------------------------------------
// Flash attention v5 (unchanged — measured 190us/half):
// Br=128, Bc=64, 256 threads. QK fp16 2-pass; PV fp16 single. 128KB smem.
// ---------------------------------------------------------------------------
#define FLB_SMEM (65536 + 32768 + 32768)
#define NQT (SEQ / 128)   // 16

__global__ __launch_bounds__(256) void flash_mma(
    const __half* __restrict__ Qhi, const __half* __restrict__ Qlo,
    const __half* __restrict__ Kf, const __half* __restrict__ Vf,
    __half* __restrict__ Oa, int bh_base)
{
    extern __shared__ char dsm[];
    const uint32_t smQ = smem_u32(dsm);
    const uint32_t smK = smQ + 65536u;
    const uint32_t smV = smK + 32768u;

    const int tid = threadIdx.x;
    const int w = tid >> 5;
    const int lane = tid & 31;
    const int qt = NQT - 1 - blockIdx.x;
    const int bh = bh_base + blockIdx.y;
    const int b = bh / NHEADS;
    const int h = bh % NHEADS;
    const int kvh = h / NREP;
    const int q0 = qt * 128;

    const size_t qoff = ((size_t)(b * NHEADS + h) * SEQ + q0) * HD;
    const size_t kvbase = (size_t)(b * NKV + kvh) * SEQ * HD;

    auto load_K = [&](int stage, int kt) {
        const int k0 = kt * 64;
        const uint32_t stb = smK + stage * 16384u;
#pragma unroll
        for (int it = 0; it < 4; it++) {
            int g = tid + it * 256;
            int r = g >> 4;
            int gg = g & 15;
            const __half* src = Kf + kvbase + (size_t)(k0 + r) * HD + gg * 8;
            uint32_t dst = stb + (gg >> 2) * 4096u
                         + sw64((uint32_t)(r * 64 + (gg & 3) * 16));
            CP_ASYNC16(dst, src);
        }
    };
    auto load_V = [&](int stage, int kt) {
        const int k0 = kt * 64;
        const uint32_t stb = smV + stage * 16384u;
#pragma unroll
        for (int it = 0; it < 4; it++) {
            int g = tid + it * 256;
            int r = g >> 4;
            int gg = g & 15;
            const __half* src = Vf + kvbase + (size_t)(k0 + r) * HD + gg * 8;
            uint32_t dst = stb + (gg >> 2) * 4096u
                         + sw64((uint32_t)(r * 64 + (gg & 3) * 16));
            CP_ASYNC16(dst, src);
        }
    };

    {
#pragma unroll
        for (int it = 0; it < 16; it++) {
            int g = tid + it * 256;
            int arr = g >> 11;
            int rem = g & 2047;
            int r = rem >> 4;
            int gg = rem & 15;
            const __half* src = (arr ? Qlo : Qhi) + qoff + (size_t)r * HD + gg * 8;
            uint32_t dst = smQ + arr * 32768u + (gg >> 2) * 8192u
                         + sw64((uint32_t)(r * 64 + (gg & 3) * 16));
            CP_ASYNC16(dst, src);
        }
    }
    load_K(0, 0);
    CP_COMMIT();
    const int nkt = 2 * qt + 2;
    if (nkt > 1) load_K(1, 1);
    load_V(0, 0);
    CP_COMMIT();

    float o[16][4];
#pragma unroll
    for (int nt = 0; nt < 16; nt++)
#pragma unroll
        for (int e = 0; e < 4; e++) o[nt][e] = 0.f;
    float m_prev[2] = {NEG_BIG, NEG_BIG};
    float l[2] = {0.f, 0.f};

    const uint32_t a_row = w * 16 + (lane & 15);
    const uint32_t a_c16 = (lane >> 4) * 16;
    const uint32_t b_row = ((lane >> 4) & 1) * 8 + (lane & 7);
    const uint32_t b_c16 = ((lane >> 3) & 1) * 16;
    const uint32_t v_row = (lane & 7) + ((lane >> 3) & 1) * 8;
    const uint32_t v_c16 = (lane >> 4) * 16;

    float sA[8][4], sB[8][4];

    auto do_qk = [&](int kt, float (*sn)[4]) {
        const uint32_t Kst = smK + (uint32_t)(kt & 1) * 16384u;
#pragma unroll
        for (int j = 0; j < 8; j++)
#pragma unroll
            for (int e = 0; e < 4; e++) sn[j][e] = 0.f;
#pragma unroll
        for (int ks = 0; ks < 8; ks++) {
            const uint32_t qoffb = (ks >> 1) * 8192u
                + sw64(a_row * 64 + (ks & 1) * 32 + a_c16);
            uint32_t qh[4], ql[4];
            ldsm4(qh, smQ + qoffb);
            ldsm4(ql, smQ + 32768u + qoffb);
            uint32_t kh[4][4];
#pragma unroll
            for (int p = 0; p < 4; p++) {
                const uint32_t koffb = (ks >> 1) * 4096u
                    + sw64((b_row + p * 16) * 64 + (ks & 1) * 32 + b_c16);
                ldsm4(kh[p], Kst + koffb);
            }
#pragma unroll
            for (int j = 0; j < 8; j++)
                mma_hf(sn[j], qh, &kh[j >> 1][(j & 1) * 2]);
#pragma unroll
            for (int j = 0; j < 8; j++)
                mma_hf(sn[j], ql, &kh[j >> 1][(j & 1) * 2]);
        }
    };

    auto do_softmax_pv = [&](int kt, float (*s)[4]) {
        const bool diag = (kt >= nkt - 2);
        if (diag) {
            const int k0 = kt * 64;
#pragma unroll
            for (int j = 0; j < 8; j++)
#pragma unroll
                for (int e = 0; e < 4; e++) {
                    const int cglob = k0 + j * 8 + (lane & 3) * 2 + (e & 1);
                    const int rglob = q0 + w * 16 + (lane >> 2) + (e >> 1) * 8;
                    if (cglob > rglob) s[j][e] = NEG_BIG;
                }
        }

        float mx0 = NEG_BIG, mx1 = NEG_BIG;
#pragma unroll
        for (int j = 0; j < 8; j++) {
            mx0 = fmaxf(mx0, fmaxf(s[j][0], s[j][1]));
            mx1 = fmaxf(mx1, fmaxf(s[j][2], s[j][3]));
        }
        mx0 = fmaxf(mx0, __shfl_xor_sync(0xffffffffu, mx0, 1));
        mx0 = fmaxf(mx0, __shfl_xor_sync(0xffffffffu, mx0, 2));
        mx1 = fmaxf(mx1, __shfl_xor_sync(0xffffffffu, mx1, 1));
        mx1 = fmaxf(mx1, __shfl_xor_sync(0xffffffffu, mx1, 2));

        const float mn0 = fmaxf(m_prev[0], mx0);
        const float mn1 = fmaxf(m_prev[1], mx1);
        const float corr0 = ex2(m_prev[0] - mn0);
        const float corr1 = ex2(m_prev[1] - mn1);
        m_prev[0] = mn0;
        m_prev[1] = mn1;

        float rs0 = 0.f, rs1 = 0.f;
#pragma unroll
        for (int j = 0; j < 8; j++) {
            s[j][0] = ex2(s[j][0] - mn0);
            s[j][1] = ex2(s[j][1] - mn0);
            s[j][2] = ex2(s[j][2] - mn1);
            s[j][3] = ex2(s[j][3] - mn1);
            rs0 += s[j][0] + s[j][1];
            rs1 += s[j][2] + s[j][3];
        }
        rs0 += __shfl_xor_sync(0xffffffffu, rs0, 1);
        rs0 += __shfl_xor_sync(0xffffffffu, rs0, 2);
        rs1 += __shfl_xor_sync(0xffffffffu, rs1, 1);
        rs1 += __shfl_xor_sync(0xffffffffu, rs1, 2);
        l[0] = l[0] * corr0 + rs0;
        l[1] = l[1] * corr1 + rs1;

#pragma unroll
        for (int nt = 0; nt < 16; nt++) {
            o[nt][0] *= corr0; o[nt][1] *= corr0;
            o[nt][2] *= corr1; o[nt][3] *= corr1;
        }

        const uint32_t Vst = smV + (uint32_t)(kt & 1) * 16384u;
#pragma unroll
        for (int ks = 0; ks < 4; ks++) {
            const int j0 = 2 * ks, j1 = 2 * ks + 1;
            uint32_t pf[4];
            pf[0] = packhf(s[j0][0], s[j0][1]);
            pf[1] = packhf(s[j0][2], s[j0][3]);
            pf[2] = packhf(s[j1][0], s[j1][1]);
            pf[3] = packhf(s[j1][2], s[j1][3]);
#pragma unroll
            for (int c = 0; c < 4; c++) {
                uint32_t vh0[4], vh1[4];
                const uint32_t vb0 = c * 4096u + sw64((ks * 16 + v_row) * 64 + v_c16);
                const uint32_t vb1 = c * 4096u + sw64((ks * 16 + v_row) * 64 + 32 + v_c16);
                ldsm4t(vh0, Vst + vb0);
                ldsm4t(vh1, Vst + vb1);
                mma_hf(o[c * 4 + 0], pf, vh0 + 0);
                mma_hf(o[c * 4 + 1], pf, vh0 + 2);
                mma_hf(o[c * 4 + 2], pf, vh1 + 0);
                mma_hf(o[c * 4 + 3], pf, vh1 + 2);
            }
        }
    };

    CP_WAIT1();
    __syncthreads();
    do_qk(0, sA);

    auto body = [&](int i, float (*scur)[4], float (*snxt)[4]) {
        CP_WAIT0();
        __syncthreads();
        if (i + 1 < nkt) load_V((i + 1) & 1, i + 1);
        if (i + 2 < nkt) load_K((i + 2) & 1, i + 2);
        CP_COMMIT();
        if (i + 1 < nkt) do_qk(i + 1, snxt);
        do_softmax_pv(i, scur);
    };

    for (int i = 0; i < nkt; i += 2) {
        body(i, sA, sB);
        if (i + 1 < nkt) body(i + 1, sB, sA);
    }

    const float inv0 = 1.f / l[0];
    const float inv1 = 1.f / l[1];
    const int row0 = q0 + w * 16 + (lane >> 2);
#pragma unroll
    for (int nt = 0; nt < 16; nt++) {
        const int d = nt * 8 + (lane & 3) * 2;
        const size_t o0 = ((size_t)(b * SEQ + row0) * NHEADS + h) * HD + d;
        const size_t o1 = ((size_t)(b * SEQ + row0 + 8) * NHEADS + h) * HD + d;
        *(uint32_t*)&Oa[o0] = packhf(o[nt][0] * inv0, o[nt][1] * inv0);
        *(uint32_t*)&Oa[o1] = packhf(o[nt][2] * inv1, o[nt][3] * inv1);
    }
}

// ---------------------------------------------------------------------------
extern "C" void kernel_launch(void* const* d_in, const int* in_sizes, int n_in,
                              void* d_out, int out_size)
{
    const float* X    = (const float*)d_in[0];
    const float* cosb = (const float*)d_in[1];
    const float* sinb = (const float*)d_in[2];
    const float* wq = (const float*)d_in[4];
    const float* wk = (const float*)d_in[5];
    const float* wv = (const float*)d_in[6];
    const float* wo = (const float*)d_in[7];
    float* out = (float*)d_out;

    void *pq, *pk, *pv;
    cudaGetSymbolAddress(&pq, g_q);
    cudaGetSymbolAddress(&pk, g_k);
    cudaGetSymbolAddress(&pv, g_v);
    float* Qb = (float*)pq;
    float* Kb = (float*)pk;
    float* Vb = (float*)pv;

    void *pxf, *pwh, *pwl, *poh, *paf;
    cudaGetSymbolAddress(&pxf, g_xf16);
    cudaGetSymbolAddress(&pwh, g_wqkvT_hi); cudaGetSymbolAddress(&pwl, g_wqkvT_lo);
    cudaGetSymbolAddress(&poh, g_woT_hi);
    cudaGetSymbolAddress(&paf, g_af16);
    __half *Xf = (__half*)pxf;
    __half *WHi = (__half*)pwh, *WLo = (__half*)pwl;
    __half *WoHi = (__half*)poh;
    __half *Af = (__half*)paf;

    void *pfqh, *pfql, *pfkf, *pfvf;
    cudaGetSymbolAddress(&pfqh, g_qhi); cudaGetSymbolAddress(&pfql, g_qlo);
    cudaGetSymbolAddress(&pfkf, g_kf16); cudaGetSymbolAddress(&pfvf, g_vf16);
    __half *FQh = (__half*)pfqh, *FQl = (__half*)pfql;
    __half *FKf = (__half*)pfkf, *FVf = (__half*)pfvf;

    static bool attr_set = false;
    if (!attr_set) {
        cudaFuncSetAttribute((const void*)gemm_qkv,
                             cudaFuncAttributeMaxDynamicSharedMemorySize, GQKV_SMEM);
        cudaFuncSetAttribute((const void*)gemm_o,
                             cudaFuncAttributeMaxDynamicSharedMemorySize, GO_SMEM);
        cudaFuncSetAttribute((const void*)flash_mma,
                             cudaFuncAttributeMaxDynamicSharedMemorySize, FLB_SMEM);
        attr_set = true;
    }

    const int M = BATCH * SEQ;   // 4096

    // 1: weight prep + X convert
    prepW_kernel<<<dim3(128, 128, 5), dim3(32, 8)>>>(
        X, wq, wk, wv, wo, Xf, WHi, WLo, WoHi);
    // 2: merged QKV projection (persistent, 2-pass)
    gemm_qkv<<<NPERSIST, 256, GQKV_SMEM>>>(Xf, WHi, WLo, Qb, Kb, Vb, M, 6144, HID);
    // 3: flash preps
    {
        int total = PREP_QT + PREP_KT + PREP_VT;
        prep_kernel<<<(total + 255) / 256, 256>>>(Qb, Kb, Vb, cosb, sinb,
                                                  FQh, FQl, FKf, FVf);
    }
    // 4+5: flash attention
    flash_mma<<<dim3(NQT, 32), 256, FLB_SMEM>>>(FQh, FQl, FKf, FVf, Af, 0);
    flash_mma<<<dim3(NQT, 32), 256, FLB_SMEM>>>(FQh, FQl, FKf, FVf, Af, 32);
    // 6: output projection (persistent, single-pass)
    gemm_o<<<NPERSIST, 256, GO_SMEM>>>(Af, WoHi, out, M, HID, 4096);

    (void)in_sizes; (void)n_in; (void)out_size;
}

// round 16
// speedup vs baseline: 1.0435x; 1.0435x over previous
#include <cuda_runtime.h>
#include <cuda_bf16.h>
#include <cuda_fp16.h>
#include <math.h>
#include <stdint.h>

// Problem constants
#define BATCH   2
#define SEQ     2048
#define HID     4096
#define NHEADS  32
#define NKV     8
#define NREP    4
#define HD      128
#define SCALING 0.08838834764831845f           // 128^-0.5
#define QSCALE  0.1275429555686623f            // SCALING * log2(e)
#define NEG_BIG (-1.0e30f)
#define NPERSIST 296                            // 2 CTAs/SM x 148 SMs

// ---------------------------------------------------------------------------
// Scratch (device globals)
// ---------------------------------------------------------------------------
__device__ float g_q[BATCH * NHEADS * SEQ * HD];
__device__ float g_k[BATCH * NKV * SEQ * HD];
__device__ float g_v[BATCH * NKV * SEQ * HD];

__device__ __half g_xf16[4096 * 4096];
__device__ __half g_wqkvT_hi[6144 * 4096], g_wqkvT_lo[6144 * 4096];
__device__ __half g_woT_hi[4096 * 4096];
__device__ __half g_af16[4096 * 4096];

// flash operands: all single fp16 now (QK 1-pass, PV 1-pass)
__device__ __half g_qf16[BATCH * NHEADS * SEQ * HD];
__device__ __half g_kf16[BATCH * NKV * SEQ * HD];
__device__ __half g_vf16[BATCH * NKV * SEQ * HD];

// ---------------------------------------------------------------------------
// PTX helpers
// ---------------------------------------------------------------------------
__device__ __forceinline__ uint32_t smem_u32(const void* p) {
    uint32_t a;
    asm("{ .reg .u64 t; cvta.to.shared.u64 t, %1; cvt.u32.u64 %0, t; }"
        : "=r"(a) : "l"(p));
    return a;
}

#define CP_ASYNC16(dst, src) \
    asm volatile("cp.async.cg.shared.global [%0], [%1], 16;" :: "r"(dst), "l"(src) : "memory")
#define CP_COMMIT() asm volatile("cp.async.commit_group;" ::: "memory")
#define CP_WAIT0()  asm volatile("cp.async.wait_group 0;" ::: "memory")
#define CP_WAIT1()  asm volatile("cp.async.wait_group 1;" ::: "memory")

__device__ __forceinline__ void ldsm4(uint32_t* r, uint32_t addr) {
    asm volatile("ldmatrix.sync.aligned.m8n8.x4.shared.b16 {%0,%1,%2,%3}, [%4];"
        : "=r"(r[0]), "=r"(r[1]), "=r"(r[2]), "=r"(r[3]) : "r"(addr));
}
__device__ __forceinline__ void ldsm4t(uint32_t* r, uint32_t addr) {
    asm volatile("ldmatrix.sync.aligned.m8n8.x4.trans.shared.b16 {%0,%1,%2,%3}, [%4];"
        : "=r"(r[0]), "=r"(r[1]), "=r"(r[2]), "=r"(r[3]) : "r"(addr));
}

__device__ __forceinline__ void mma_hf(float* d, const uint32_t* a, const uint32_t* b) {
    asm volatile(
        "mma.sync.aligned.m16n8k16.row.col.f32.f16.f16.f32 "
        "{%0,%1,%2,%3}, {%4,%5,%6,%7}, {%8,%9}, {%0,%1,%2,%3};"
        : "+f"(d[0]), "+f"(d[1]), "+f"(d[2]), "+f"(d[3])
        : "r"(a[0]), "r"(a[1]), "r"(a[2]), "r"(a[3]), "r"(b[0]), "r"(b[1]));
}

__device__ __forceinline__ uint32_t sw64(uint32_t off) {
    return off ^ ((off >> 3) & 0x30);
}
__device__ __forceinline__ uint32_t sw128(uint32_t off) {
    return off ^ ((off >> 3) & 0x70);
}

__device__ __forceinline__ uint32_t packhf(float lo, float hi) {
    uint32_t r;
    asm("cvt.rn.f16x2.f32 %0, %1, %2;" : "=r"(r) : "f"(hi), "f"(lo));
    return r;
}

__device__ __forceinline__ float ex2(float x) {
    float r;
    asm("ex2.approx.f32 %0, %1;" : "=f"(r) : "f"(x));
    return r;
}

// ---------------------------------------------------------------------------
// prepW: z=0..2 merged QKV weight transpose+split; z=3 wo (hi only); z=4 X cvt.
// ---------------------------------------------------------------------------
__global__ void prepW_kernel(
    const float* __restrict__ X,
    const float* __restrict__ wq, const float* __restrict__ wk,
    const float* __restrict__ wv, const float* __restrict__ wo,
    __half* __restrict__ Xf,
    __half* __restrict__ qkvh, __half* __restrict__ qkvl,
    __half* __restrict__ oh)
{
    const int z = blockIdx.z;
    const int tx = threadIdx.x, ty = threadIdx.y;

    if (z == 4) {
        size_t g = ((size_t)blockIdx.y * gridDim.x + blockIdx.x) * 256 + (ty * 32 + tx);
        size_t i = g * 4;
        float4 v = *(const float4*)(X + i);
        uint32_t p0 = packhf(v.x, v.y);
        uint32_t p1 = packhf(v.z, v.w);
        *(uint2*)(Xf + i) = make_uint2(p0, p1);
        return;
    }

    const float* in;
    int N, rbase;
    bool want_lo;
    __half *hi, *lo;
    if (z == 0)      { in = wq; hi = qkvh; lo = qkvl; N = 4096; rbase = 0;    want_lo = true; }
    else if (z == 1) { in = wk; hi = qkvh; lo = qkvl; N = 1024; rbase = 4096; want_lo = true; }
    else if (z == 2) { in = wv; hi = qkvh; lo = qkvl; N = 1024; rbase = 5120; want_lo = true; }
    else             { in = wo; hi = oh;   lo = oh;   N = 4096; rbase = 0;    want_lo = false; }
    const int n0 = blockIdx.x * 32;
    if (n0 >= N) return;
    const int K = 4096;
    const int k0 = blockIdx.y * 32;

    __shared__ float t[32][33];
    for (int i = ty; i < 32; i += 8)
        t[i][tx] = in[(size_t)(k0 + i) * N + n0 + tx];
    __syncthreads();
    for (int i = ty; i < 32; i += 8) {
        float a = t[tx][i];
        __half h = __float2half_rn(a);
        size_t o = (size_t)(rbase + n0 + i) * K + k0 + tx;
        hi[o] = h;
        if (want_lo)
            lo[o] = __float2half_rn(a - __half2float(h));
    }
}

// ---------------------------------------------------------------------------
// prep: ropeQ (fp16 single, pre-scaled) + ropeK (fp16 single) + cvtV (fp16)
// ---------------------------------------------------------------------------
#define PREP_QT (BATCH * NHEADS * SEQ * 64)
#define PREP_KT (BATCH * NKV * SEQ * 64)
#define PREP_VT (BATCH * NKV * SEQ * HD / 4)

__global__ void prep_kernel(
    const float* __restrict__ Qb, const float* __restrict__ Kb,
    const float* __restrict__ Vb,
    const float* __restrict__ cosb, const float* __restrict__ sinb,
    __half* __restrict__ FQf, __half* __restrict__ FKf, __half* __restrict__ Vf)
{
    int idx = blockIdx.x * blockDim.x + threadIdx.x;
    if (idx < PREP_QT) {
        const int d = idx & 63;
        const int row = idx >> 6;
        const int s = row & (SEQ - 1);
        const int b = (row / SEQ) / NHEADS;
        const float* xr = Qb + (size_t)row * HD;
        const float* cb = cosb + ((size_t)b * SEQ + s) * HD;
        const float* sb = sinb + ((size_t)b * SEQ + s) * HD;
        const float x0 = xr[d];
        const float x1 = xr[d + 64];
        const float y0 = (x0 * cb[d]      - x1 * sb[d])      * QSCALE;
        const float y1 = (x1 * cb[d + 64] + x0 * sb[d + 64]) * QSCALE;
        const size_t o = (size_t)row * HD + d;
        FQf[o]      = __float2half_rn(y0);
        FQf[o + 64] = __float2half_rn(y1);
    } else if (idx < PREP_QT + PREP_KT) {
        int i2 = idx - PREP_QT;
        const int d = i2 & 63;
        const int row = i2 >> 6;
        const int s = row & (SEQ - 1);
        const int b = (row / SEQ) / NKV;
        const float* xr = Kb + (size_t)row * HD;
        const float* cb = cosb + ((size_t)b * SEQ + s) * HD;
        const float* sb = sinb + ((size_t)b * SEQ + s) * HD;
        const float x0 = xr[d];
        const float x1 = xr[d + 64];
        const float y0 = x0 * cb[d]      - x1 * sb[d];
        const float y1 = x1 * cb[d + 64] + x0 * sb[d + 64];
        const size_t o = (size_t)row * HD + d;
        FKf[o]      = __float2half_rn(y0);
        FKf[o + 64] = __float2half_rn(y1);
    } else if (idx < PREP_QT + PREP_KT + PREP_VT) {
        int i = (idx - PREP_QT - PREP_KT) * 4;
        float4 v = *(const float4*)(Vb + i);
        uint32_t p0 = packhf(v.x, v.y);
        uint32_t p1 = packhf(v.z, v.w);
        *(uint2*)(Vf + i) = make_uint2(p0, p1);
    }
}

// ---------------------------------------------------------------------------
// Persistent QKV GEMM: BM=BN=128, BK=64, 256 thr, 2 CTAs/SM.
// Q/K column tiles (n0 < 5120): 2-pass. V column tiles (n0 >= 5120): 1-pass.
// ---------------------------------------------------------------------------
#define GQKV_SMEM (2 * 49152)
#define QKV_TILES (48 * 32)

__global__ __launch_bounds__(256, 2) void gemm_qkv(
    const __half* __restrict__ A,
    const __half* __restrict__ Bhi, const __half* __restrict__ Blo,
    float* __restrict__ Qo, float* __restrict__ Ko, float* __restrict__ Vo,
    int M, int N, int K)
{
    extern __shared__ char dsm[];
    const uint32_t sm_base = smem_u32(dsm);

    const int tid = threadIdx.x;
    const int wid = tid >> 5;
    const int lane = tid & 31;
    const int wm = wid & 3;
    const int wn = wid >> 2;

    const uint32_t a_row = wm * 32 + (lane & 15);
    const uint32_t a_c16 = (lane >> 4) * 16;
    const uint32_t b_row = wn * 64 + ((lane >> 4) & 1) * 8 + (lane & 7);
    const uint32_t b_c16 = ((lane >> 3) & 1) * 16;
    const int NC = K >> 6;

    for (int t = blockIdx.x; t < QKV_TILES; t += NPERSIST) {
        const int m0 = (t / 48) * 128;
        const int n0 = (t % 48) * 128;
        const bool vtile = (n0 >= 5120);

        auto load_chunk = [&](int stage, int c) {
            const int k0 = c << 6;
            const uint32_t stb = sm_base + stage * 49152u;
#pragma unroll
            for (int it = 0; it < 12; it++) {
                int g = tid + it * 256;
                int arr = g >> 10;
                if (arr == 2 && vtile) continue;
                int rem = g & 1023;
                int r = rem >> 3;
                int gg = rem & 7;
                int rowg = (arr == 0 ? m0 : n0) + r;
                const __half* base = (arr == 0) ? A : (arr == 1 ? Bhi : Blo);
                const __half* src = base + (size_t)rowg * K + k0 + gg * 8;
                uint32_t off = sw128((uint32_t)(r * 128 + gg * 16));
                CP_ASYNC16(stb + arr * 16384u + off, src);
            }
            CP_COMMIT();
        };

        float acc[2][8][4];
#pragma unroll
        for (int mt = 0; mt < 2; mt++)
#pragma unroll
            for (int nt = 0; nt < 8; nt++)
#pragma unroll
                for (int i = 0; i < 4; i++) acc[mt][nt][i] = 0.f;

        load_chunk(0, 0);

        for (int c = 0; c < NC; c++) {
            if (c + 1 < NC) {
                load_chunk((c + 1) & 1, c + 1);
                CP_WAIT1();
            } else {
                CP_WAIT0();
            }
            __syncthreads();

            const uint32_t stb = sm_base + (uint32_t)(c & 1) * 49152u;
            const uint32_t Ab = stb, Bh = stb + 16384u, Bl = stb + 32768u;

#pragma unroll
            for (int kt = 0; kt < 4; kt++) {
                uint32_t af[2][4], bhf[4][4], blf[4][4];
#pragma unroll
                for (int mt = 0; mt < 2; mt++) {
                    uint32_t off = sw128((a_row + mt * 16) * 128 + kt * 32 + a_c16);
                    ldsm4(af[mt], Ab + off);
                }
#pragma unroll
                for (int p = 0; p < 4; p++) {
                    uint32_t off = sw128((b_row + p * 16) * 128 + kt * 32 + b_c16);
                    ldsm4(bhf[p], Bh + off);
                    if (!vtile) ldsm4(blf[p], Bl + off);
                }
#pragma unroll
                for (int mt = 0; mt < 2; mt++)
#pragma unroll
                    for (int nt = 0; nt < 8; nt++)
                        mma_hf(acc[mt][nt], af[mt], &bhf[nt >> 1][(nt & 1) * 2]);
                if (!vtile) {
#pragma unroll
                    for (int mt = 0; mt < 2; mt++)
#pragma unroll
                        for (int nt = 0; nt < 8; nt++)
                            mma_hf(acc[mt][nt], af[mt], &blf[nt >> 1][(nt & 1) * 2]);
                }
            }
            __syncthreads();
        }

        const int mr = m0 + wm * 32 + (lane >> 2);
        const int nc = n0 + wn * 64 + (lane & 3) * 2;
#pragma unroll
        for (int mt = 0; mt < 2; mt++) {
#pragma unroll
            for (int nt = 0; nt < 8; nt++) {
#pragma unroll
                for (int half = 0; half < 2; half++) {
                    const int m = mr + mt * 16 + half * 8;
                    const int n = nc + nt * 8;
                    float2 v = make_float2(acc[mt][nt][half * 2], acc[mt][nt][half * 2 + 1]);
                    const int b = m >> 11;
                    const int s = m & (SEQ - 1);
                    const int d = n & (HD - 1);
                    if (n < 4096) {
                        const int h = n >> 7;
                        *(float2*)&Qo[((size_t)(b * NHEADS + h) * SEQ + s) * HD + d] = v;
                    } else if (n < 5120) {
                        const int kv = (n - 4096) >> 7;
                        *(float2*)&Ko[((size_t)(b * NKV + kv) * SEQ + s) * HD + d] = v;
                    } else {
                        const int kv = (n - 5120) >> 7;
                        *(float2*)&Vo[((size_t)(b * NKV + kv) * SEQ + s) * HD + d] = v;
                    }
                }
            }
        }
    }
}

// ---------------------------------------------------------------------------
// Persistent O-projection GEMM: BM=BN=128, BK=64, 256 thr, single-pass fp16.
// ---------------------------------------------------------------------------
#define GO_SMEM (2 * 32768)
#define O_TILES (32 * 32)

__global__ __launch_bounds__(256, 2) void gemm_o(
    const __half* __restrict__ A, const __half* __restrict__ B,
    float* __restrict__ C, int M, int N, int K)
{
    extern __shared__ char dsm[];
    const uint32_t sm_base = smem_u32(dsm);

    const int tid = threadIdx.x;
    const int wid = tid >> 5;
    const int lane = tid & 31;
    const int wm = wid & 3;
    const int wn = wid >> 2;

    const uint32_t a_row = wm * 32 + (lane & 15);
    const uint32_t a_c16 = (lane >> 4) * 16;
    const uint32_t b_row = wn * 64 + ((lane >> 4) & 1) * 8 + (lane & 7);
    const uint32_t b_c16 = ((lane >> 3) & 1) * 16;
    const int NC = K >> 6;

    for (int t = blockIdx.x; t < O_TILES; t += NPERSIST) {
        const int m0 = (t / 32) * 128;
        const int n0 = (t % 32) * 128;

        auto load_chunk = [&](int stage, int c) {
            const int k0 = c << 6;
            const uint32_t stb = sm_base + stage * 32768u;
#pragma unroll
            for (int it = 0; it < 8; it++) {
                int g = tid + it * 256;
                int arr = g >> 10;
                int rem = g & 1023;
                int r = rem >> 3;
                int gg = rem & 7;
                int rowg = (arr == 0 ? m0 : n0) + r;
                const __half* src = (arr == 0 ? A : B) + (size_t)rowg * K + k0 + gg * 8;
                uint32_t off = sw128((uint32_t)(r * 128 + gg * 16));
                CP_ASYNC16(stb + arr * 16384u + off, src);
            }
            CP_COMMIT();
        };

        float acc[2][8][4];
#pragma unroll
        for (int mt = 0; mt < 2; mt++)
#pragma unroll
            for (int nt = 0; nt < 8; nt++)
#pragma unroll
                for (int i = 0; i < 4; i++) acc[mt][nt][i] = 0.f;

        load_chunk(0, 0);

        for (int c = 0; c < NC; c++) {
            if (c + 1 < NC) {
                load_chunk((c + 1) & 1, c + 1);
                CP_WAIT1();
            } else {
                CP_WAIT0();
            }
            __syncthreads();

            const uint32_t stb = sm_base + (uint32_t)(c & 1) * 32768u;
            const uint32_t Ab = stb, Bb = stb + 16384u;

#pragma unroll
            for (int kt = 0; kt < 4; kt++) {
                uint32_t af[2][4], bf[4][4];
#pragma unroll
                for (int mt = 0; mt < 2; mt++) {
                    uint32_t off = sw128((a_row + mt * 16) * 128 + kt * 32 + a_c16);
                    ldsm4(af[mt], Ab + off);
                }
#pragma unroll
                for (int p = 0; p < 4; p++) {
                    uint32_t off = sw128((b_row + p * 16) * 128 + kt * 32 + b_c16);
                    ldsm4(bf[p], Bb + off);
                }
#pragma unroll
                for (int mt = 0; mt < 2; mt++)
#pragma unroll
                    for (int nt = 0; nt < 8; nt++)
                        mma_hf(acc[mt][nt], af[mt], &bf[nt >> 1][(nt & 1) * 2]);
            }
            __syncthreads();
        }

        const int mr = m0 + wm * 32 + (lane >> 2);
        const int nc = n0 + wn * 64 + (lane & 3) * 2;
#pragma unroll
        for (int mt = 0; mt < 2; mt++)
#pragma unroll
            for (int nt = 0; nt < 8; nt++)
#pragma unroll
                for (int half = 0; half < 2; half++) {
                    const int m = mr + mt * 16 + half * 8;
                    const int n = nc + nt * 8;
                    *(float2*)&C[(size_t)m * N + n] =
                        make_float2(acc[mt][nt][half * 2], acc[mt][nt][half * 2 + 1]);
                }
    }
}

// ---------------------------------------------------------------------------
// Flash attention v6: Br=128, Bc=64, 256 threads.
// QK fp16 SINGLE-pass (Q and K single fp16) pipelined; PV fp16 single.
// Q 32KB + K ring 2x16KB + V ring 2x16KB = 96KB.
// ---------------------------------------------------------------------------
#define FLB_SMEM (32768 + 32768 + 32768)
#define NQT (SEQ / 128)   // 16

__global__ __launch_bounds__(256) void flash_mma(
    const __half* __restrict__ Qf,
    const __half* __restrict__ Kf, const __half* __restrict__ Vf,
    __half* __restrict__ Oa, int bh_base)
{
    extern __shared__ char dsm[];
    const uint32_t smQ = smem_u32(dsm);
    const uint32_t smK = smQ + 32768u;
    const uint32_t smV = smK + 32768u;

    const int tid = threadIdx.x;
    const int w = tid >> 5;
    const int lane = tid & 31;
    const int qt = NQT - 1 - blockIdx.x;
    const int bh = bh_base + blockIdx.y;
    const int b = bh / NHEADS;
    const int h = bh % NHEADS;
    const int kvh = h / NREP;
    const int q0 = qt * 128;

    const size_t qoff = ((size_t)(b * NHEADS + h) * SEQ + q0) * HD;
    const size_t kvbase = (size_t)(b * NKV + kvh) * SEQ * HD;

    auto load_K = [&](int stage, int kt) {
        const int k0 = kt * 64;
        const uint32_t stb = smK + stage * 16384u;
#pragma unroll
        for (int it = 0; it < 4; it++) {
            int g = tid + it * 256;
            int r = g >> 4;
            int gg = g & 15;
            const __half* src = Kf + kvbase + (size_t)(k0 + r) * HD + gg * 8;
            uint32_t dst = stb + (gg >> 2) * 4096u
                         + sw64((uint32_t)(r * 64 + (gg & 3) * 16));
            CP_ASYNC16(dst, src);
        }
    };
    auto load_V = [&](int stage, int kt) {
        const int k0 = kt * 64;
        const uint32_t stb = smV + stage * 16384u;
#pragma unroll
        for (int it = 0; it < 4; it++) {
            int g = tid + it * 256;
            int r = g >> 4;
            int gg = g & 15;
            const __half* src = Vf + kvbase + (size_t)(k0 + r) * HD + gg * 8;
            uint32_t dst = stb + (gg >> 2) * 4096u
                         + sw64((uint32_t)(r * 64 + (gg & 3) * 16));
            CP_ASYNC16(dst, src);
        }
    };

    // prologue: group A = {Q, K0}; group B = {K1, V0}
    {
#pragma unroll
        for (int it = 0; it < 8; it++) {
            int g = tid + it * 256;          // 2048 granules: 128 rows x 16
            int r = g >> 4;
            int gg = g & 15;
            const __half* src = Qf + qoff + (size_t)r * HD + gg * 8;
            uint32_t dst = smQ + (gg >> 2) * 8192u
                         + sw64((uint32_t)(r * 64 + (gg & 3) * 16));
            CP_ASYNC16(dst, src);
        }
    }
    load_K(0, 0);
    CP_COMMIT();
    const int nkt = 2 * qt + 2;
    if (nkt > 1) load_K(1, 1);
    load_V(0, 0);
    CP_COMMIT();

    float o[16][4];
#pragma unroll
    for (int nt = 0; nt < 16; nt++)
#pragma unroll
        for (int e = 0; e < 4; e++) o[nt][e] = 0.f;
    float m_prev[2] = {NEG_BIG, NEG_BIG};
    float l[2] = {0.f, 0.f};

    const uint32_t a_row = w * 16 + (lane & 15);
    const uint32_t a_c16 = (lane >> 4) * 16;
    const uint32_t b_row = ((lane >> 4) & 1) * 8 + (lane & 7);
    const uint32_t b_c16 = ((lane >> 3) & 1) * 16;
    const uint32_t v_row = (lane & 7) + ((lane >> 3) & 1) * 8;
    const uint32_t v_c16 = (lane >> 4) * 16;

    float sA[8][4], sB[8][4];

    auto do_qk = [&](int kt, float (*sn)[4]) {
        const uint32_t Kst = smK + (uint32_t)(kt & 1) * 16384u;
#pragma unroll
        for (int j = 0; j < 8; j++)
#pragma unroll
            for (int e = 0; e < 4; e++) sn[j][e] = 0.f;
#pragma unroll
        for (int ks = 0; ks < 8; ks++) {
            const uint32_t qoffb = (ks >> 1) * 8192u
                + sw64(a_row * 64 + (ks & 1) * 32 + a_c16);
            uint32_t qh[4];
            ldsm4(qh, smQ + qoffb);
            uint32_t kh[4][4];
#pragma unroll
            for (int p = 0; p < 4; p++) {
                const uint32_t koffb = (ks >> 1) * 4096u
                    + sw64((b_row + p * 16) * 64 + (ks & 1) * 32 + b_c16);
                ldsm4(kh[p], Kst + koffb);
            }
#pragma unroll
            for (int j = 0; j < 8; j++)
                mma_hf(sn[j], qh, &kh[j >> 1][(j & 1) * 2]);
        }
    };

    auto do_softmax_pv = [&](int kt, float (*s)[4]) {
        const bool diag = (kt >= nkt - 2);
        if (diag) {
            const int k0 = kt * 64;
#pragma unroll
            for (int j = 0; j < 8; j++)
#pragma unroll
                for (int e = 0; e < 4; e++) {
                    const int cglob = k0 + j * 8 + (lane & 3) * 2 + (e & 1);
                    const int rglob = q0 + w * 16 + (lane >> 2) + (e >> 1) * 8;
                    if (cglob > rglob) s[j][e] = NEG_BIG;
                }
        }

        float mx0 = NEG_BIG, mx1 = NEG_BIG;
#pragma unroll
        for (int j = 0; j < 8; j++) {
            mx0 = fmaxf(mx0, fmaxf(s[j][0], s[j][1]));
            mx1 = fmaxf(mx1, fmaxf(s[j][2], s[j][3]));
        }
        mx0 = fmaxf(mx0, __shfl_xor_sync(0xffffffffu, mx0, 1));
        mx0 = fmaxf(mx0, __shfl_xor_sync(0xffffffffu, mx0, 2));
        mx1 = fmaxf(mx1, __shfl_xor_sync(0xffffffffu, mx1, 1));
        mx1 = fmaxf(mx1, __shfl_xor_sync(0xffffffffu, mx1, 2));

        const float mn0 = fmaxf(m_prev[0], mx0);
        const float mn1 = fmaxf(m_prev[1], mx1);
        const float corr0 = ex2(m_prev[0] - mn0);
        const float corr1 = ex2(m_prev[1] - mn1);
        m_prev[0] = mn0;
        m_prev[1] = mn1;

        float rs0 = 0.f, rs1 = 0.f;
#pragma unroll
        for (int j = 0; j < 8; j++) {
            s[j][0] = ex2(s[j][0] - mn0);
            s[j][1] = ex2(s[j][1] - mn0);
            s[j][2] = ex2(s[j][2] - mn1);
            s[j][3] = ex2(s[j][3] - mn1);
            rs0 += s[j][0] + s[j][1];
            rs1 += s[j][2] + s[j][3];
        }
        rs0 += __shfl_xor_sync(0xffffffffu, rs0, 1);
        rs0 += __shfl_xor_sync(0xffffffffu, rs0, 2);
        rs1 += __shfl_xor_sync(0xffffffffu, rs1, 1);
        rs1 += __shfl_xor_sync(0xffffffffu, rs1, 2);
        l[0] = l[0] * corr0 + rs0;
        l[1] = l[1] * corr1 + rs1;

#pragma unroll
        for (int nt = 0; nt < 16; nt++) {
            o[nt][0] *= corr0; o[nt][1] *= corr0;
            o[nt][2] *= corr1; o[nt][3] *= corr1;
        }

        const uint32_t Vst = smV + (uint32_t)(kt & 1) * 16384u;
#pragma unroll
        for (int ks = 0; ks < 4; ks++) {
            const int j0 = 2 * ks, j1 = 2 * ks + 1;
            uint32_t pf[4];
            pf[0] = packhf(s[j0][0], s[j0][1]);
            pf[1] = packhf(s[j0][2], s[j0][3]);
            pf[2] = packhf(s[j1][0], s[j1][1]);
            pf[3] = packhf(s[j1][2], s[j1][3]);
#pragma unroll
            for (int c = 0; c < 4; c++) {
                uint32_t vh0[4], vh1[4];
                const uint32_t vb0 = c * 4096u + sw64((ks * 16 + v_row) * 64 + v_c16);
                const uint32_t vb1 = c * 4096u + sw64((ks * 16 + v_row) * 64 + 32 + v_c16);
                ldsm4t(vh0, Vst + vb0);
                ldsm4t(vh1, Vst + vb1);
                mma_hf(o[c * 4 + 0], pf, vh0 + 0);
                mma_hf(o[c * 4 + 1], pf, vh0 + 2);
                mma_hf(o[c * 4 + 2], pf, vh1 + 0);
                mma_hf(o[c * 4 + 3], pf, vh1 + 2);
            }
        }
    };

    CP_WAIT1();
    __syncthreads();
    do_qk(0, sA);

    auto body = [&](int i, float (*scur)[4], float (*snxt)[4]) {
        CP_WAIT0();
        __syncthreads();
        if (i + 1 < nkt) load_V((i + 1) & 1, i + 1);
        if (i + 2 < nkt) load_K((i + 2) & 1, i + 2);
        CP_COMMIT();
        if (i + 1 < nkt) do_qk(i + 1, snxt);
        do_softmax_pv(i, scur);
    };

    for (int i = 0; i < nkt; i += 2) {
        body(i, sA, sB);
        if (i + 1 < nkt) body(i + 1, sB, sA);
    }

    const float inv0 = 1.f / l[0];
    const float inv1 = 1.f / l[1];
    const int row0 = q0 + w * 16 + (lane >> 2);
#pragma unroll
    for (int nt = 0; nt < 16; nt++) {
        const int d = nt * 8 + (lane & 3) * 2;
        const size_t o0 = ((size_t)(b * SEQ + row0) * NHEADS + h) * HD + d;
        const size_t o1 = ((size_t)(b * SEQ + row0 + 8) * NHEADS + h) * HD + d;
        *(uint32_t*)&Oa[o0] = packhf(o[nt][0] * inv0, o[nt][1] * inv0);
        *(uint32_t*)&Oa[o1] = packhf(o[nt][2] * inv1, o[nt][3] * inv1);
    }
}

// ---------------------------------------------------------------------------
extern "C" void kernel_launch(void* const* d_in, const int* in_sizes, int n_in,
                              void* d_out, int out_size)
{
    const float* X    = (const float*)d_in[0];
    const float* cosb = (const float*)d_in[1];
    const float* sinb = (const float*)d_in[2];
    const float* wq = (const float*)d_in[4];
    const float* wk = (const float*)d_in[5];
    const float* wv = (const float*)d_in[6];
    const float* wo = (const float*)d_in[7];
    float* out = (float*)d_out;

    void *pq, *pk, *pv;
    cudaGetSymbolAddress(&pq, g_q);
    cudaGetSymbolAddress(&pk, g_k);
    cudaGetSymbolAddress(&pv, g_v);
    float* Qb = (float*)pq;
    float* Kb = (float*)pk;
    float* Vb = (float*)pv;

    void *pxf, *pwh, *pwl, *poh, *paf;
    cudaGetSymbolAddress(&pxf, g_xf16);
    cudaGetSymbolAddress(&pwh, g_wqkvT_hi); cudaGetSymbolAddress(&pwl, g_wqkvT_lo);
    cudaGetSymbolAddress(&poh, g_woT_hi);
    cudaGetSymbolAddress(&paf, g_af16);
    __half *Xf = (__half*)pxf;
    __half *WHi = (__half*)pwh, *WLo = (__half*)pwl;
    __half *WoHi = (__half*)poh;
    __half *Af = (__half*)paf;

    void *pfqf, *pfkf, *pfvf;
    cudaGetSymbolAddress(&pfqf, g_qf16);
    cudaGetSymbolAddress(&pfkf, g_kf16);
    cudaGetSymbolAddress(&pfvf, g_vf16);
    __half *FQf = (__half*)pfqf;
    __half *FKf = (__half*)pfkf, *FVf = (__half*)pfvf;

    static bool attr_set = false;
    if (!attr_set) {
        cudaFuncSetAttribute((const void*)gemm_qkv,
                             cudaFuncAttributeMaxDynamicSharedMemorySize, GQKV_SMEM);
        cudaFuncSetAttribute((const void*)gemm_o,
                             cudaFuncAttributeMaxDynamicSharedMemorySize, GO_SMEM);
        cudaFuncSetAttribute((const void*)flash_mma,
                             cudaFuncAttributeMaxDynamicSharedMemorySize, FLB_SMEM);
        attr_set = true;
    }

    const int M = BATCH * SEQ;   // 4096

    // 1: weight prep + X convert
    prepW_kernel<<<dim3(128, 128, 5), dim3(32, 8)>>>(
        X, wq, wk, wv, wo, Xf, WHi, WLo, WoHi);
    // 2: merged QKV projection (persistent; QK 2-pass, V 1-pass)
    gemm_qkv<<<NPERSIST, 256, GQKV_SMEM>>>(Xf, WHi, WLo, Qb, Kb, Vb, M, 6144, HID);
    // 3: flash preps
    {
        int total = PREP_QT + PREP_KT + PREP_VT;
        prep_kernel<<<(total + 255) / 256, 256>>>(Qb, Kb, Vb, cosb, sinb,
                                                  FQf, FKf, FVf);
    }
    // 4+5: flash attention
    flash_mma<<<dim3(NQT, 32), 256, FLB_SMEM>>>(FQf, FKf, FVf, Af, 0);
    flash_mma<<<dim3(NQT, 32), 256, FLB_SMEM>>>(FQf, FKf, FVf, Af, 32);
    // 6: output projection (persistent, single-pass)
    gemm_o<<<NPERSIST, 256, GO_SMEM>>>(Af, WoHi, out, M, HID, 4096);

    (void)in_sizes; (void)n_in; (void)out_size;
}

// round 17
// speedup vs baseline: 1.0639x; 1.0196x over previous
#include <cuda_runtime.h>
#include <cuda_bf16.h>
#include <cuda_fp16.h>
#include <math.h>
#include <stdint.h>

// Problem constants
#define BATCH   2
#define SEQ     2048
#define HID     4096
#define NHEADS  32
#define NKV     8
#define NREP    4
#define HD      128
#define SCALING 0.08838834764831845f           // 128^-0.5
#define QSCALE  0.1275429555686623f            // SCALING * log2(e)
#define NEG_BIG (-1.0e30f)
#define NPERSIST 296                            // 2 CTAs/SM x 148 SMs

// ---------------------------------------------------------------------------
// Scratch (device globals)
// ---------------------------------------------------------------------------
__device__ float g_q[BATCH * NHEADS * SEQ * HD];
__device__ float g_k[BATCH * NKV * SEQ * HD];

__device__ __half g_xf16[4096 * 4096];
__device__ __half g_wqkvT_hi[6144 * 4096], g_wqkvT_lo[6144 * 4096];
__device__ __half g_woT_hi[4096 * 4096];
__device__ __half g_af16[4096 * 4096];

// flash operands (single fp16)
__device__ __half g_qf16[BATCH * NHEADS * SEQ * HD];
__device__ __half g_kf16[BATCH * NKV * SEQ * HD];
__device__ __half g_vf16[BATCH * NKV * SEQ * HD];

// ---------------------------------------------------------------------------
// PTX helpers
// ---------------------------------------------------------------------------
__device__ __forceinline__ uint32_t smem_u32(const void* p) {
    uint32_t a;
    asm("{ .reg .u64 t; cvta.to.shared.u64 t, %1; cvt.u32.u64 %0, t; }"
        : "=r"(a) : "l"(p));
    return a;
}

#define CP_ASYNC16(dst, src) \
    asm volatile("cp.async.cg.shared.global [%0], [%1], 16;" :: "r"(dst), "l"(src) : "memory")
#define CP_COMMIT() asm volatile("cp.async.commit_group;" ::: "memory")
#define CP_WAIT0()  asm volatile("cp.async.wait_group 0;" ::: "memory")
#define CP_WAIT1()  asm volatile("cp.async.wait_group 1;" ::: "memory")

__device__ __forceinline__ void ldsm4(uint32_t* r, uint32_t addr) {
    asm volatile("ldmatrix.sync.aligned.m8n8.x4.shared.b16 {%0,%1,%2,%3}, [%4];"
        : "=r"(r[0]), "=r"(r[1]), "=r"(r[2]), "=r"(r[3]) : "r"(addr));
}
__device__ __forceinline__ void ldsm4t(uint32_t* r, uint32_t addr) {
    asm volatile("ldmatrix.sync.aligned.m8n8.x4.trans.shared.b16 {%0,%1,%2,%3}, [%4];"
        : "=r"(r[0]), "=r"(r[1]), "=r"(r[2]), "=r"(r[3]) : "r"(addr));
}

__device__ __forceinline__ void mma_hf(float* d, const uint32_t* a, const uint32_t* b) {
    asm volatile(
        "mma.sync.aligned.m16n8k16.row.col.f32.f16.f16.f32 "
        "{%0,%1,%2,%3}, {%4,%5,%6,%7}, {%8,%9}, {%0,%1,%2,%3};"
        : "+f"(d[0]), "+f"(d[1]), "+f"(d[2]), "+f"(d[3])
        : "r"(a[0]), "r"(a[1]), "r"(a[2]), "r"(a[3]), "r"(b[0]), "r"(b[1]));
}

__device__ __forceinline__ uint32_t sw64(uint32_t off) {
    return off ^ ((off >> 3) & 0x30);
}
__device__ __forceinline__ uint32_t sw128(uint32_t off) {
    return off ^ ((off >> 3) & 0x70);
}

__device__ __forceinline__ uint32_t packhf(float lo, float hi) {
    uint32_t r;
    asm("cvt.rn.f16x2.f32 %0, %1, %2;" : "=r"(r) : "f"(hi), "f"(lo));
    return r;
}

__device__ __forceinline__ float ex2(float x) {
    float r;
    asm("ex2.approx.f32 %0, %1;" : "=f"(r) : "f"(x));
    return r;
}

// ---------------------------------------------------------------------------
// Launch 1: X fp32 -> fp16
// ---------------------------------------------------------------------------
__global__ void cvtX_kernel(const float* __restrict__ X, __half* __restrict__ Xf)
{
    size_t i = ((size_t)blockIdx.x * 256 + threadIdx.x) * 4;
    float4 v = *(const float4*)(X + i);
    uint32_t p0 = packhf(v.x, v.y);
    uint32_t p1 = packhf(v.z, v.w);
    *(uint2*)(Xf + i) = make_uint2(p0, p1);
}

// ---------------------------------------------------------------------------
// Launch 2: merged QKV weight transpose+split (hi/lo)
// ---------------------------------------------------------------------------
__global__ void splitWqkv_kernel(
    const float* __restrict__ wq, const float* __restrict__ wk,
    const float* __restrict__ wv,
    __half* __restrict__ qkvh, __half* __restrict__ qkvl)
{
    const int z = blockIdx.z;
    const float* in;
    int N, rbase;
    if (z == 0)      { in = wq; N = 4096; rbase = 0; }
    else if (z == 1) { in = wk; N = 1024; rbase = 4096; }
    else             { in = wv; N = 1024; rbase = 5120; }
    const int n0 = blockIdx.x * 32;
    if (n0 >= N) return;
    const int K = 4096;
    const int k0 = blockIdx.y * 32;
    const int tx = threadIdx.x, ty = threadIdx.y;

    __shared__ float t[32][33];
    for (int i = ty; i < 32; i += 8)
        t[i][tx] = in[(size_t)(k0 + i) * N + n0 + tx];
    __syncthreads();
    for (int i = ty; i < 32; i += 8) {
        float a = t[tx][i];
        __half h = __float2half_rn(a);
        size_t o = (size_t)(rbase + n0 + i) * K + k0 + tx;
        qkvh[o] = h;
        qkvl[o] = __float2half_rn(a - __half2float(h));
    }
}

// ---------------------------------------------------------------------------
// Launch 3: wo transpose (hi only)
// ---------------------------------------------------------------------------
__global__ void splitWo_kernel(const float* __restrict__ wo, __half* __restrict__ oh)
{
    const int n0 = blockIdx.x * 32;
    const int K = 4096;
    const int k0 = blockIdx.y * 32;
    const int tx = threadIdx.x, ty = threadIdx.y;

    __shared__ float t[32][33];
    for (int i = ty; i < 32; i += 8)
        t[i][tx] = wo[(size_t)(k0 + i) * 4096 + n0 + tx];
    __syncthreads();
    for (int i = ty; i < 32; i += 8) {
        size_t o = (size_t)(n0 + i) * K + k0 + tx;
        oh[o] = __float2half_rn(t[tx][i]);
    }
}

// ---------------------------------------------------------------------------
// Launch 5: prep = ropeQ + ropeK (fp16 single; V handled by QKV epilogue)
// ---------------------------------------------------------------------------
#define PREP_QT (BATCH * NHEADS * SEQ * 64)
#define PREP_KT (BATCH * NKV * SEQ * 64)

__global__ void prep_kernel(
    const float* __restrict__ Qb, const float* __restrict__ Kb,
    const float* __restrict__ cosb, const float* __restrict__ sinb,
    __half* __restrict__ FQf, __half* __restrict__ FKf)
{
    int idx = blockIdx.x * blockDim.x + threadIdx.x;
    if (idx < PREP_QT) {
        const int d = idx & 63;
        const int row = idx >> 6;
        const int s = row & (SEQ - 1);
        const int b = (row / SEQ) / NHEADS;
        const float* xr = Qb + (size_t)row * HD;
        const float* cb = cosb + ((size_t)b * SEQ + s) * HD;
        const float* sb = sinb + ((size_t)b * SEQ + s) * HD;
        const float x0 = xr[d];
        const float x1 = xr[d + 64];
        const float y0 = (x0 * cb[d]      - x1 * sb[d])      * QSCALE;
        const float y1 = (x1 * cb[d + 64] + x0 * sb[d + 64]) * QSCALE;
        const size_t o = (size_t)row * HD + d;
        FQf[o]      = __float2half_rn(y0);
        FQf[o + 64] = __float2half_rn(y1);
    } else if (idx < PREP_QT + PREP_KT) {
        int i2 = idx - PREP_QT;
        const int d = i2 & 63;
        const int row = i2 >> 6;
        const int s = row & (SEQ - 1);
        const int b = (row / SEQ) / NKV;
        const float* xr = Kb + (size_t)row * HD;
        const float* cb = cosb + ((size_t)b * SEQ + s) * HD;
        const float* sb = sinb + ((size_t)b * SEQ + s) * HD;
        const float x0 = xr[d];
        const float x1 = xr[d + 64];
        const float y0 = x0 * cb[d]      - x1 * sb[d];
        const float y1 = x1 * cb[d + 64] + x0 * sb[d + 64];
        const size_t o = (size_t)row * HD + d;
        FKf[o]      = __float2half_rn(y0);
        FKf[o + 64] = __float2half_rn(y1);
    }
}

// ---------------------------------------------------------------------------
// Launch 4 (ncu slot): persistent QKV GEMM. BM=BN=128, BK=64, 256 thr.
// Q/K tiles (n0 < 5120): 2-pass -> fp32 out. V tiles: 1-pass -> fp16 out.
// ---------------------------------------------------------------------------
#define GQKV_SMEM (2 * 49152)
#define QKV_TILES (48 * 32)

__global__ __launch_bounds__(256, 2) void gemm_qkv(
    const __half* __restrict__ A,
    const __half* __restrict__ Bhi, const __half* __restrict__ Blo,
    float* __restrict__ Qo, float* __restrict__ Ko, __half* __restrict__ Vo,
    int M, int N, int K)
{
    extern __shared__ char dsm[];
    const uint32_t sm_base = smem_u32(dsm);

    const int tid = threadIdx.x;
    const int wid = tid >> 5;
    const int lane = tid & 31;
    const int wm = wid & 3;
    const int wn = wid >> 2;

    const uint32_t a_row = wm * 32 + (lane & 15);
    const uint32_t a_c16 = (lane >> 4) * 16;
    const uint32_t b_row = wn * 64 + ((lane >> 4) & 1) * 8 + (lane & 7);
    const uint32_t b_c16 = ((lane >> 3) & 1) * 16;
    const int NC = K >> 6;

    for (int t = blockIdx.x; t < QKV_TILES; t += NPERSIST) {
        const int m0 = (t / 48) * 128;
        const int n0 = (t % 48) * 128;
        const bool vtile = (n0 >= 5120);

        auto load_chunk = [&](int stage, int c) {
            const int k0 = c << 6;
            const uint32_t stb = sm_base + stage * 49152u;
#pragma unroll
            for (int it = 0; it < 12; it++) {
                int g = tid + it * 256;
                int arr = g >> 10;
                if (arr == 2 && vtile) continue;
                int rem = g & 1023;
                int r = rem >> 3;
                int gg = rem & 7;
                int rowg = (arr == 0 ? m0 : n0) + r;
                const __half* base = (arr == 0) ? A : (arr == 1 ? Bhi : Blo);
                const __half* src = base + (size_t)rowg * K + k0 + gg * 8;
                uint32_t off = sw128((uint32_t)(r * 128 + gg * 16));
                CP_ASYNC16(stb + arr * 16384u + off, src);
            }
            CP_COMMIT();
        };

        float acc[2][8][4];
#pragma unroll
        for (int mt = 0; mt < 2; mt++)
#pragma unroll
            for (int nt = 0; nt < 8; nt++)
#pragma unroll
                for (int i = 0; i < 4; i++) acc[mt][nt][i] = 0.f;

        load_chunk(0, 0);

        for (int c = 0; c < NC; c++) {
            if (c + 1 < NC) {
                load_chunk((c + 1) & 1, c + 1);
                CP_WAIT1();
            } else {
                CP_WAIT0();
            }
            __syncthreads();

            const uint32_t stb = sm_base + (uint32_t)(c & 1) * 49152u;
            const uint32_t Ab = stb, Bh = stb + 16384u, Bl = stb + 32768u;

#pragma unroll
            for (int kt = 0; kt < 4; kt++) {
                uint32_t af[2][4], bhf[4][4], blf[4][4];
#pragma unroll
                for (int mt = 0; mt < 2; mt++) {
                    uint32_t off = sw128((a_row + mt * 16) * 128 + kt * 32 + a_c16);
                    ldsm4(af[mt], Ab + off);
                }
#pragma unroll
                for (int p = 0; p < 4; p++) {
                    uint32_t off = sw128((b_row + p * 16) * 128 + kt * 32 + b_c16);
                    ldsm4(bhf[p], Bh + off);
                    if (!vtile) ldsm4(blf[p], Bl + off);
                }
#pragma unroll
                for (int mt = 0; mt < 2; mt++)
#pragma unroll
                    for (int nt = 0; nt < 8; nt++)
                        mma_hf(acc[mt][nt], af[mt], &bhf[nt >> 1][(nt & 1) * 2]);
                if (!vtile) {
#pragma unroll
                    for (int mt = 0; mt < 2; mt++)
#pragma unroll
                        for (int nt = 0; nt < 8; nt++)
                            mma_hf(acc[mt][nt], af[mt], &blf[nt >> 1][(nt & 1) * 2]);
                }
            }
            __syncthreads();
        }

        const int mr = m0 + wm * 32 + (lane >> 2);
        const int nc = n0 + wn * 64 + (lane & 3) * 2;
#pragma unroll
        for (int mt = 0; mt < 2; mt++) {
#pragma unroll
            for (int nt = 0; nt < 8; nt++) {
#pragma unroll
                for (int half = 0; half < 2; half++) {
                    const int m = mr + mt * 16 + half * 8;
                    const int n = nc + nt * 8;
                    const int b = m >> 11;
                    const int s = m & (SEQ - 1);
                    const int d = n & (HD - 1);
                    if (n < 4096) {
                        const int h = n >> 7;
                        *(float2*)&Qo[((size_t)(b * NHEADS + h) * SEQ + s) * HD + d] =
                            make_float2(acc[mt][nt][half * 2], acc[mt][nt][half * 2 + 1]);
                    } else if (n < 5120) {
                        const int kv = (n - 4096) >> 7;
                        *(float2*)&Ko[((size_t)(b * NKV + kv) * SEQ + s) * HD + d] =
                            make_float2(acc[mt][nt][half * 2], acc[mt][nt][half * 2 + 1]);
                    } else {
                        const int kv = (n - 5120) >> 7;
                        *(uint32_t*)&Vo[((size_t)(b * NKV + kv) * SEQ + s) * HD + d] =
                            packhf(acc[mt][nt][half * 2], acc[mt][nt][half * 2 + 1]);
                    }
                }
            }
        }
    }
}

// ---------------------------------------------------------------------------
// Launch 7: persistent O-projection GEMM. Single-pass fp16.
// ---------------------------------------------------------------------------
#define GO_SMEM (2 * 32768)
#define O_TILES (32 * 32)

__global__ __launch_bounds__(256, 2) void gemm_o(
    const __half* __restrict__ A, const __half* __restrict__ B,
    float* __restrict__ C, int M, int N, int K)
{
    extern __shared__ char dsm[];
    const uint32_t sm_base = smem_u32(dsm);

    const int tid = threadIdx.x;
    const int wid = tid >> 5;
    const int lane = tid & 31;
    const int wm = wid & 3;
    const int wn = wid >> 2;

    const uint32_t a_row = wm * 32 + (lane & 15);
    const uint32_t a_c16 = (lane >> 4) * 16;
    const uint32_t b_row = wn * 64 + ((lane >> 4) & 1) * 8 + (lane & 7);
    const uint32_t b_c16 = ((lane >> 3) & 1) * 16;
    const int NC = K >> 6;

    for (int t = blockIdx.x; t < O_TILES; t += NPERSIST) {
        const int m0 = (t / 32) * 128;
        const int n0 = (t % 32) * 128;

        auto load_chunk = [&](int stage, int c) {
            const int k0 = c << 6;
            const uint32_t stb = sm_base + stage * 32768u;
#pragma unroll
            for (int it = 0; it < 8; it++) {
                int g = tid + it * 256;
                int arr = g >> 10;
                int rem = g & 1023;
                int r = rem >> 3;
                int gg = rem & 7;
                int rowg = (arr == 0 ? m0 : n0) + r;
                const __half* src = (arr == 0 ? A : B) + (size_t)rowg * K + k0 + gg * 8;
                uint32_t off = sw128((uint32_t)(r * 128 + gg * 16));
                CP_ASYNC16(stb + arr * 16384u + off, src);
            }
            CP_COMMIT();
        };

        float acc[2][8][4];
#pragma unroll
        for (int mt = 0; mt < 2; mt++)
#pragma unroll
            for (int nt = 0; nt < 8; nt++)
#pragma unroll
                for (int i = 0; i < 4; i++) acc[mt][nt][i] = 0.f;

        load_chunk(0, 0);

        for (int c = 0; c < NC; c++) {
            if (c + 1 < NC) {
                load_chunk((c + 1) & 1, c + 1);
                CP_WAIT1();
            } else {
                CP_WAIT0();
            }
            __syncthreads();

            const uint32_t stb = sm_base + (uint32_t)(c & 1) * 32768u;
            const uint32_t Ab = stb, Bb = stb + 16384u;

#pragma unroll
            for (int kt = 0; kt < 4; kt++) {
                uint32_t af[2][4], bf[4][4];
#pragma unroll
                for (int mt = 0; mt < 2; mt++) {
                    uint32_t off = sw128((a_row + mt * 16) * 128 + kt * 32 + a_c16);
                    ldsm4(af[mt], Ab + off);
                }
#pragma unroll
                for (int p = 0; p < 4; p++) {
                    uint32_t off = sw128((b_row + p * 16) * 128 + kt * 32 + b_c16);
                    ldsm4(bf[p], Bb + off);
                }
#pragma unroll
                for (int mt = 0; mt < 2; mt++)
#pragma unroll
                    for (int nt = 0; nt < 8; nt++)
                        mma_hf(acc[mt][nt], af[mt], &bf[nt >> 1][(nt & 1) * 2]);
            }
            __syncthreads();
        }

        const int mr = m0 + wm * 32 + (lane >> 2);
        const int nc = n0 + wn * 64 + (lane & 3) * 2;
#pragma unroll
        for (int mt = 0; mt < 2; mt++)
#pragma unroll
            for (int nt = 0; nt < 8; nt++)
#pragma unroll
                for (int half = 0; half < 2; half++) {
                    const int m = mr + mt * 16 + half * 8;
                    const int n = nc + nt * 8;
                    *(float2*)&C[(size_t)m * N + n] =
                        make_float2(acc[mt][nt][half * 2], acc[mt][nt][half * 2 + 1]);
                }
    }
}

// ---------------------------------------------------------------------------
// Launch 6: flash attention v6 (single merged launch, grid NQT x 64).
// QK fp16 1-pass pipelined; PV fp16 1-pass. 96KB smem.
// ---------------------------------------------------------------------------
#define FLB_SMEM (32768 + 32768 + 32768)
#define NQT (SEQ / 128)   // 16

__global__ __launch_bounds__(256) void flash_mma(
    const __half* __restrict__ Qf,
    const __half* __restrict__ Kf, const __half* __restrict__ Vf,
    __half* __restrict__ Oa)
{
    extern __shared__ char dsm[];
    const uint32_t smQ = smem_u32(dsm);
    const uint32_t smK = smQ + 32768u;
    const uint32_t smV = smK + 32768u;

    const int tid = threadIdx.x;
    const int w = tid >> 5;
    const int lane = tid & 31;
    const int qt = NQT - 1 - blockIdx.x;     // longest first
    const int bh = blockIdx.y;
    const int b = bh / NHEADS;
    const int h = bh % NHEADS;
    const int kvh = h / NREP;
    const int q0 = qt * 128;

    const size_t qoff = ((size_t)(b * NHEADS + h) * SEQ + q0) * HD;
    const size_t kvbase = (size_t)(b * NKV + kvh) * SEQ * HD;

    auto load_K = [&](int stage, int kt) {
        const int k0 = kt * 64;
        const uint32_t stb = smK + stage * 16384u;
#pragma unroll
        for (int it = 0; it < 4; it++) {
            int g = tid + it * 256;
            int r = g >> 4;
            int gg = g & 15;
            const __half* src = Kf + kvbase + (size_t)(k0 + r) * HD + gg * 8;
            uint32_t dst = stb + (gg >> 2) * 4096u
                         + sw64((uint32_t)(r * 64 + (gg & 3) * 16));
            CP_ASYNC16(dst, src);
        }
    };
    auto load_V = [&](int stage, int kt) {
        const int k0 = kt * 64;
        const uint32_t stb = smV + stage * 16384u;
#pragma unroll
        for (int it = 0; it < 4; it++) {
            int g = tid + it * 256;
            int r = g >> 4;
            int gg = g & 15;
            const __half* src = Vf + kvbase + (size_t)(k0 + r) * HD + gg * 8;
            uint32_t dst = stb + (gg >> 2) * 4096u
                         + sw64((uint32_t)(r * 64 + (gg & 3) * 16));
            CP_ASYNC16(dst, src);
        }
    };

    {
#pragma unroll
        for (int it = 0; it < 8; it++) {
            int g = tid + it * 256;
            int r = g >> 4;
            int gg = g & 15;
            const __half* src = Qf + qoff + (size_t)r * HD + gg * 8;
            uint32_t dst = smQ + (gg >> 2) * 8192u
                         + sw64((uint32_t)(r * 64 + (gg & 3) * 16));
            CP_ASYNC16(dst, src);
        }
    }
    load_K(0, 0);
    CP_COMMIT();
    const int nkt = 2 * qt + 2;
    if (nkt > 1) load_K(1, 1);
    load_V(0, 0);
    CP_COMMIT();

    float o[16][4];
#pragma unroll
    for (int nt = 0; nt < 16; nt++)
#pragma unroll
        for (int e = 0; e < 4; e++) o[nt][e] = 0.f;
    float m_prev[2] = {NEG_BIG, NEG_BIG};
    float l[2] = {0.f, 0.f};

    const uint32_t a_row = w * 16 + (lane & 15);
    const uint32_t a_c16 = (lane >> 4) * 16;
    const uint32_t b_row = ((lane >> 4) & 1) * 8 + (lane & 7);
    const uint32_t b_c16 = ((lane >> 3) & 1) * 16;
    const uint32_t v_row = (lane & 7) + ((lane >> 3) & 1) * 8;
    const uint32_t v_c16 = (lane >> 4) * 16;

    float sA[8][4], sB[8][4];

    auto do_qk = [&](int kt, float (*sn)[4]) {
        const uint32_t Kst = smK + (uint32_t)(kt & 1) * 16384u;
#pragma unroll
        for (int j = 0; j < 8; j++)
#pragma unroll
            for (int e = 0; e < 4; e++) sn[j][e] = 0.f;
#pragma unroll
        for (int ks = 0; ks < 8; ks++) {
            const uint32_t qoffb = (ks >> 1) * 8192u
                + sw64(a_row * 64 + (ks & 1) * 32 + a_c16);
            uint32_t qh[4];
            ldsm4(qh, smQ + qoffb);
            uint32_t kh[4][4];
#pragma unroll
            for (int p = 0; p < 4; p++) {
                const uint32_t koffb = (ks >> 1) * 4096u
                    + sw64((b_row + p * 16) * 64 + (ks & 1) * 32 + b_c16);
                ldsm4(kh[p], Kst + koffb);
            }
#pragma unroll
            for (int j = 0; j < 8; j++)
                mma_hf(sn[j], qh, &kh[j >> 1][(j & 1) * 2]);
        }
    };

    auto do_softmax_pv = [&](int kt, float (*s)[4]) {
        const bool diag = (kt >= nkt - 2);
        if (diag) {
            const int k0 = kt * 64;
#pragma unroll
            for (int j = 0; j < 8; j++)
#pragma unroll
                for (int e = 0; e < 4; e++) {
                    const int cglob = k0 + j * 8 + (lane & 3) * 2 + (e & 1);
                    const int rglob = q0 + w * 16 + (lane >> 2) + (e >> 1) * 8;
                    if (cglob > rglob) s[j][e] = NEG_BIG;
                }
        }

        float mx0 = NEG_BIG, mx1 = NEG_BIG;
#pragma unroll
        for (int j = 0; j < 8; j++) {
            mx0 = fmaxf(mx0, fmaxf(s[j][0], s[j][1]));
            mx1 = fmaxf(mx1, fmaxf(s[j][2], s[j][3]));
        }
        mx0 = fmaxf(mx0, __shfl_xor_sync(0xffffffffu, mx0, 1));
        mx0 = fmaxf(mx0, __shfl_xor_sync(0xffffffffu, mx0, 2));
        mx1 = fmaxf(mx1, __shfl_xor_sync(0xffffffffu, mx1, 1));
        mx1 = fmaxf(mx1, __shfl_xor_sync(0xffffffffu, mx1, 2));

        const float mn0 = fmaxf(m_prev[0], mx0);
        const float mn1 = fmaxf(m_prev[1], mx1);
        const float corr0 = ex2(m_prev[0] - mn0);
        const float corr1 = ex2(m_prev[1] - mn1);
        m_prev[0] = mn0;
        m_prev[1] = mn1;

        float rs0 = 0.f, rs1 = 0.f;
#pragma unroll
        for (int j = 0; j < 8; j++) {
            s[j][0] = ex2(s[j][0] - mn0);
            s[j][1] = ex2(s[j][1] - mn0);
            s[j][2] = ex2(s[j][2] - mn1);
            s[j][3] = ex2(s[j][3] - mn1);
            rs0 += s[j][0] + s[j][1];
            rs1 += s[j][2] + s[j][3];
        }
        rs0 += __shfl_xor_sync(0xffffffffu, rs0, 1);
        rs0 += __shfl_xor_sync(0xffffffffu, rs0, 2);
        rs1 += __shfl_xor_sync(0xffffffffu, rs1, 1);
        rs1 += __shfl_xor_sync(0xffffffffu, rs1, 2);
        l[0] = l[0] * corr0 + rs0;
        l[1] = l[1] * corr1 + rs1;

#pragma unroll
        for (int nt = 0; nt < 16; nt++) {
            o[nt][0] *= corr0; o[nt][1] *= corr0;
            o[nt][2] *= corr1; o[nt][3] *= corr1;
        }

        const uint32_t Vst = smV + (uint32_t)(kt & 1) * 16384u;
#pragma unroll
        for (int ks = 0; ks < 4; ks++) {
            const int j0 = 2 * ks, j1 = 2 * ks + 1;
            uint32_t pf[4];
            pf[0] = packhf(s[j0][0], s[j0][1]);
            pf[1] = packhf(s[j0][2], s[j0][3]);
            pf[2] = packhf(s[j1][0], s[j1][1]);
            pf[3] = packhf(s[j1][2], s[j1][3]);
#pragma unroll
            for (int c = 0; c < 4; c++) {
                uint32_t vh0[4], vh1[4];
                const uint32_t vb0 = c * 4096u + sw64((ks * 16 + v_row) * 64 + v_c16);
                const uint32_t vb1 = c * 4096u + sw64((ks * 16 + v_row) * 64 + 32 + v_c16);
                ldsm4t(vh0, Vst + vb0);
                ldsm4t(vh1, Vst + vb1);
                mma_hf(o[c * 4 + 0], pf, vh0 + 0);
                mma_hf(o[c * 4 + 1], pf, vh0 + 2);
                mma_hf(o[c * 4 + 2], pf, vh1 + 0);
                mma_hf(o[c * 4 + 3], pf, vh1 + 2);
            }
        }
    };

    CP_WAIT1();
    __syncthreads();
    do_qk(0, sA);

    auto body = [&](int i, float (*scur)[4], float (*snxt)[4]) {
        CP_WAIT0();
        __syncthreads();
        if (i + 1 < nkt) load_V((i + 1) & 1, i + 1);
        if (i + 2 < nkt) load_K((i + 2) & 1, i + 2);
        CP_COMMIT();
        if (i + 1 < nkt) do_qk(i + 1, snxt);
        do_softmax_pv(i, scur);
    };

    for (int i = 0; i < nkt; i += 2) {
        body(i, sA, sB);
        if (i + 1 < nkt) body(i + 1, sB, sA);
    }

    const float inv0 = 1.f / l[0];
    const float inv1 = 1.f / l[1];
    const int row0 = q0 + w * 16 + (lane >> 2);
#pragma unroll
    for (int nt = 0; nt < 16; nt++) {
        const int d = nt * 8 + (lane & 3) * 2;
        const size_t o0 = ((size_t)(b * SEQ + row0) * NHEADS + h) * HD + d;
        const size_t o1 = ((size_t)(b * SEQ + row0 + 8) * NHEADS + h) * HD + d;
        *(uint32_t*)&Oa[o0] = packhf(o[nt][0] * inv0, o[nt][1] * inv0);
        *(uint32_t*)&Oa[o1] = packhf(o[nt][2] * inv1, o[nt][3] * inv1);
    }
}

// ---------------------------------------------------------------------------
extern "C" void kernel_launch(void* const* d_in, const int* in_sizes, int n_in,
                              void* d_out, int out_size)
{
    const float* X    = (const float*)d_in[0];
    const float* cosb = (const float*)d_in[1];
    const float* sinb = (const float*)d_in[2];
    const float* wq = (const float*)d_in[4];
    const float* wk = (const float*)d_in[5];
    const float* wv = (const float*)d_in[6];
    const float* wo = (const float*)d_in[7];
    float* out = (float*)d_out;

    void *pq, *pk;
    cudaGetSymbolAddress(&pq, g_q);
    cudaGetSymbolAddress(&pk, g_k);
    float* Qb = (float*)pq;
    float* Kb = (float*)pk;

    void *pxf, *pwh, *pwl, *poh, *paf;
    cudaGetSymbolAddress(&pxf, g_xf16);
    cudaGetSymbolAddress(&pwh, g_wqkvT_hi); cudaGetSymbolAddress(&pwl, g_wqkvT_lo);
    cudaGetSymbolAddress(&poh, g_woT_hi);
    cudaGetSymbolAddress(&paf, g_af16);
    __half *Xf = (__half*)pxf;
    __half *WHi = (__half*)pwh, *WLo = (__half*)pwl;
    __half *WoHi = (__half*)poh;
    __half *Af = (__half*)paf;

    void *pfqf, *pfkf, *pfvf;
    cudaGetSymbolAddress(&pfqf, g_qf16);
    cudaGetSymbolAddress(&pfkf, g_kf16);
    cudaGetSymbolAddress(&pfvf, g_vf16);
    __half *FQf = (__half*)pfqf;
    __half *FKf = (__half*)pfkf, *FVf = (__half*)pfvf;

    static bool attr_set = false;
    if (!attr_set) {
        cudaFuncSetAttribute((const void*)gemm_qkv,
                             cudaFuncAttributeMaxDynamicSharedMemorySize, GQKV_SMEM);
        cudaFuncSetAttribute((const void*)gemm_o,
                             cudaFuncAttributeMaxDynamicSharedMemorySize, GO_SMEM);
        cudaFuncSetAttribute((const void*)flash_mma,
                             cudaFuncAttributeMaxDynamicSharedMemorySize, FLB_SMEM);
        attr_set = true;
    }

    const int M = BATCH * SEQ;   // 4096

    // 1: X convert
    cvtX_kernel<<<M * HID / 4 / 256, 256>>>(X, Xf);
    // 2: QKV weight split
    splitWqkv_kernel<<<dim3(128, 128, 3), dim3(32, 8)>>>(wq, wk, wv, WHi, WLo);
    // 3: wo transpose
    splitWo_kernel<<<dim3(128, 128), dim3(32, 8)>>>(wo, WoHi);
    // 4: merged QKV projection (persistent; QK 2-pass fp32 out, V 1-pass fp16 out)
    //    <-- ncu capture slot
    gemm_qkv<<<NPERSIST, 256, GQKV_SMEM>>>(Xf, WHi, WLo, Qb, Kb, FVf, M, 6144, HID);
    // 5: rope preps (Q + K)
    {
        int total = PREP_QT + PREP_KT;
        prep_kernel<<<(total + 255) / 256, 256>>>(Qb, Kb, cosb, sinb, FQf, FKf);
    }
    // 6: flash attention (single merged launch)
    flash_mma<<<dim3(NQT, BATCH * NHEADS), 256, FLB_SMEM>>>(FQf, FKf, FVf, Af);
    // 7: output projection (persistent, single-pass)
    gemm_o<<<NPERSIST, 256, GO_SMEM>>>(Af, WoHi, out, M, HID, 4096);

    (void)in_sizes; (void)n_in; (void)out_size;
}